// round 13
// baseline (speedup 1.0000x reference)
#include <cuda_runtime.h>
#include <cuda_fp16.h>
#include <math.h>
#include <stdint.h>

#define TOK   4096          // B*N
#define BSZ   4
#define NSEQ  1024
#define CDIM  1024
#define HEADS 16
#define HDIM  64
#define FFD   4096
#define LAYERS 4
#define ATT_SCALE_LOG2E 0.1803368801111244f   // 64^-0.5 * log2(e)
#define NFLAGS (TOK / 128 + 1)                // [0..31] tile flags, [32] anyWinner

// GEMM smem strides (halves)
#define LDH 72              // 64 halves + 8 pad -> 144 B row stride
#define A_TILE_H (128 * LDH)
#define B_TILE_H (256 * LDH)
#define STAGE_H (A_TILE_H + B_TILE_H)
#define GEMM_STAGES 3
#define GEMM_SMEM_BYTES (GEMM_STAGES * STAGE_H * 2)   // 165888 B

// attn smem: Q [64][72] + K [2 buf][128][72] halves
#define ATTN_Q_H (64 * LDH)
#define ATTN_K_H (2 * 128 * LDH)
#define ATTN_SMEM_BYTES ((ATTN_Q_H + ATTN_K_H) * 2)

// Scratch (device globals; no allocation allowed)
__device__ __half g_xn  [(size_t)TOK * CDIM];
__device__ __half g_qk  [(size_t)TOK * 2 * CDIM];   // [tok][Q(0..C) K(C..2C)]
__device__ __half g_attn[(size_t)TOK * CDIM];
__device__ __half g_ff  [(size_t)TOK * FFD];
__device__ int    g_flags[NFLAGS];
__device__ int    g_pbz[LAYERS];                    // proj bias nonzero
__device__ int    g_lneq[LAYERS];                   // ln1 params == ln2 params
// fp16, TRANSPOSED weights: Wt[N][K]
__device__ __half g_wq[(size_t)LAYERS * CDIM * 3 * CDIM];
__device__ __half g_wp[(size_t)LAYERS * CDIM * CDIM];
__device__ __half g_w1[(size_t)LAYERS * CDIM * FFD];
__device__ __half g_w2[(size_t)LAYERS * FFD * CDIM];

// ---------------------------------------------------------------------------
__device__ __forceinline__ void cp_async16(uint32_t s, const void* g) {
    asm volatile("cp.async.cg.shared.global [%0], [%1], 16;" :: "r"(s), "l"(g));
}
__device__ __forceinline__ void cp_commit() {
    asm volatile("cp.async.commit_group;");
}
__device__ __forceinline__ void cp_wait0() {
    asm volatile("cp.async.wait_group 0;");
}
__device__ __forceinline__ void cp_wait1() {
    asm volatile("cp.async.wait_group 1;");
}
__device__ __forceinline__ void ldsm_x4(uint32_t& r0, uint32_t& r1, uint32_t& r2,
                                        uint32_t& r3, uint32_t addr) {
    asm volatile("ldmatrix.sync.aligned.m8n8.x4.shared.b16 {%0,%1,%2,%3}, [%4];"
                 : "=r"(r0), "=r"(r1), "=r"(r2), "=r"(r3) : "r"(addr));
}
__device__ __forceinline__ void mma_f16(float* c, const uint32_t* a, const uint32_t* b) {
    asm volatile(
        "mma.sync.aligned.m16n8k16.row.col.f32.f16.f16.f32 "
        "{%0,%1,%2,%3}, {%4,%5,%6,%7}, {%8,%9}, {%0,%1,%2,%3};"
        : "+f"(c[0]), "+f"(c[1]), "+f"(c[2]), "+f"(c[3])
        : "r"(a[0]), "r"(a[1]), "r"(a[2]), "r"(a[3]), "r"(b[0]), "r"(b[1]));
}
__device__ __forceinline__ float tanh_fast(float x) {
    float y;
    asm("tanh.approx.f32 %0, %1;" : "=f"(y) : "f"(x));
    return y;
}
__device__ __forceinline__ float gelu_fast(float v) {
    const float c0 = 0.7978845608028654f, c1 = 0.044715f;
    return 0.5f * v * (1.0f + tanh_fast(c0 * (v + c1 * v * v * v)));
}
__device__ __forceinline__ float ex2(float x) {   // 2^x, HW MUFU
    float y;
    asm("ex2.approx.f32 %0, %1;" : "=f"(y) : "f"(x));
    return y;
}

// ---------------------------------------------------------------------------
// weight prep: fp32 [K,N] -> half [N,K] (transpose + convert), per-layer via z
// ---------------------------------------------------------------------------
__global__ __launch_bounds__(256)
void prep_w_kernel(const float* __restrict__ src,
                   __half* __restrict__ dst, int K, int N) {
    __shared__ __half t[64][65];
    const size_t lo = (size_t)blockIdx.z * K * N;
    const int n0 = blockIdx.x * 64, k0 = blockIdx.y * 64;
    const int tx = threadIdx.x & 15, ty = threadIdx.x >> 4;   // 16x16

    #pragma unroll
    for (int ii = 0; ii < 4; ii++) {
        const int k = k0 + ty + ii * 16;
        const float4 v = *(const float4*)&src[lo + (size_t)k * N + n0 + tx * 4];
        t[tx * 4 + 0][ty + ii * 16] = __float2half(v.x);
        t[tx * 4 + 1][ty + ii * 16] = __float2half(v.y);
        t[tx * 4 + 2][ty + ii * 16] = __float2half(v.z);
        t[tx * 4 + 3][ty + ii * 16] = __float2half(v.w);
    }
    __syncthreads();

    const int w = threadIdx.x >> 5, l = threadIdx.x & 31;
    #pragma unroll
    for (int r = 0; r < 8; r++) {
        const int n = w * 8 + r;
        __half2 h = __halves2half2(t[n][2 * l], t[n][2 * l + 1]);
        *(uint32_t*)&dst[lo + (size_t)(n0 + n) * K + k0 + 2 * l] = *(uint32_t*)&h;
    }
}

// ---------------------------------------------------------------------------
// small per-layer checks: proj bias nonzero? ln1 params == ln2 params?
// ---------------------------------------------------------------------------
__global__ void smallprep_kernel(const float* __restrict__ proj_b,
                                 const float* __restrict__ l1g,
                                 const float* __restrict__ l1b,
                                 const float* __restrict__ l2g,
                                 const float* __restrict__ l2b,
                                 int* __restrict__ pbz,
                                 int* __restrict__ lneq) {
    const int l = blockIdx.x;
    const size_t o = (size_t)l * CDIM;
    int nz = 0, neq = 0;
    for (int i = threadIdx.x; i < CDIM; i += 256) {
        nz  |= (proj_b[o + i] != 0.0f);
        neq |= (l1g[o + i] != l2g[o + i]) | (l1b[o + i] != l2b[o + i]);
    }
    nz  = __syncthreads_or(nz);
    neq = __syncthreads_or(neq);
    if (threadIdx.x == 0) { pbz[l] = nz; lneq[l] = !neq; }
}

// ---------------------------------------------------------------------------
// LayerNorm (generic): ONE WARP per row. fp32 in -> fp16 out.
// If `pos` non-null (first layer): in = x, adds pos, ALSO writes fp32 x+pos
// to `resout` (residual stream init) — fuses add_pos.
// If `flags` given (ln1), block 0 zeroes all flags (incl. anyWinner).
// If `anyw`/`lneq` given (ln2), early-exit when attention was an identity and
// ln params match ln1 (xn already holds the correct values).
// ---------------------------------------------------------------------------
__global__ __launch_bounds__(256)
void ln_kernel(const float* __restrict__ in,
               const float* __restrict__ pos,
               float* __restrict__ resout,
               const float* __restrict__ g,
               const float* __restrict__ b,
               __half* __restrict__ out,
               int* __restrict__ flags,
               const int* __restrict__ anyw,
               const int* __restrict__ lneq) {
    if (anyw && lneq && lneq[0] != 0 && anyw[0] == 0) return;
    if (flags && blockIdx.x == 0 && threadIdx.x < NFLAGS) flags[threadIdx.x] = 0;

    const int row  = blockIdx.x * 8 + (threadIdx.x >> 5);
    const int lane = threadIdx.x & 31;
    const float4* rp = (const float4*)(in + (size_t)row * CDIM);
    const float4* pp = pos ? (const float4*)(pos + (size_t)(row & (NSEQ - 1)) * CDIM)
                           : nullptr;
    float4* ro = resout ? (float4*)(resout + (size_t)row * CDIM) : nullptr;

    float4 xv[8];
    float s = 0.f, sq = 0.f;
    #pragma unroll
    for (int i = 0; i < 8; i++) {
        xv[i] = rp[i * 32 + lane];
        if (pos) {
            const float4 p = pp[i * 32 + lane];
            xv[i].x += p.x; xv[i].y += p.y; xv[i].z += p.z; xv[i].w += p.w;
            ro[i * 32 + lane] = xv[i];
        }
        s  += xv[i].x + xv[i].y + xv[i].z + xv[i].w;
        sq += xv[i].x * xv[i].x + xv[i].y * xv[i].y
            + xv[i].z * xv[i].z + xv[i].w * xv[i].w;
    }
    #pragma unroll
    for (int o = 16; o > 0; o >>= 1) {
        s  += __shfl_xor_sync(0xffffffffu, s, o);
        sq += __shfl_xor_sync(0xffffffffu, sq, o);
    }
    const float mean = s * (1.0f / CDIM);
    const float var  = sq * (1.0f / CDIM) - mean * mean;
    const float rstd = rsqrtf(var + 1e-5f);

    const float4* gp = (const float4*)g;
    const float4* bp = (const float4*)b;
    uint2* op = (uint2*)(out + (size_t)row * CDIM);
    #pragma unroll
    for (int i = 0; i < 8; i++) {
        const float4 gg = gp[i * 32 + lane];
        const float4 bb = bp[i * 32 + lane];
        __half2 h0 = __floats2half2_rn((xv[i].x - mean) * rstd * gg.x + bb.x,
                                       (xv[i].y - mean) * rstd * gg.y + bb.y);
        __half2 h1 = __floats2half2_rn((xv[i].z - mean) * rstd * gg.z + bb.z,
                                       (xv[i].w - mean) * rstd * gg.w + bb.w);
        uint2 o;
        o.x = *(uint32_t*)&h0;
        o.y = *(uint32_t*)&h1;
        op[i * 32 + lane] = o;
    }
}

// ---------------------------------------------------------------------------
// FP16 tensor-core GEMM: C = A[M,K] @ Wt[N,K]^T + bias
// 128(M) x 256(N) CTA tile, BK=64, 512 threads (2x8 warps, 64x32 warp tiles),
// 3-stage cp.async pipeline, loads interleaved into the MMA ks-loop.
// ACT 1: gelu (half out), 2: +residual (fp32 out; tile-skip via flags and
//        full early-exit when bias is known-zero), 3: plain (half out)
// ---------------------------------------------------------------------------
template <int ACT, typename OUT_T>
__global__ __launch_bounds__(512, 1)
void hgemm_kernel(const __half* __restrict__ A,
                  const __half* __restrict__ Wt,
                  const float* __restrict__ bias,
                  const float* __restrict__ res,
                  OUT_T* __restrict__ C,
                  int M, int N, int K,
                  const int* __restrict__ flags,
                  const int* __restrict__ bias_nz) {
    extern __shared__ __half smh[];

    const int tid  = threadIdx.x;
    const int lane = tid & 31;
    const int warp = tid >> 5;        // 0..15
    const int wm = warp >> 3;         // 0..1
    const int wn = warp & 7;          // 0..7
    const int bm = blockIdx.y * 128;
    const int bn = blockIdx.x * 256;

    const bool skip = (ACT == 2) && flags && (flags[blockIdx.y] == 0);
    if (ACT == 2 && skip && bias_nz && bias_nz[0] == 0) return;  // out += 0

    float acc[4][4][4];
    #pragma unroll
    for (int i = 0; i < 4; i++)
        #pragma unroll
        for (int j = 0; j < 4; j++)
            #pragma unroll
            for (int t = 0; t < 4; t++) acc[i][j][t] = 0.f;

    if (!skip) {
        // per tile: A = 1024 16B chunks (2/thread), B = 2048 (4/thread)
        auto load_chunk = [&](int kt, int st, int part) {
            __half* as = smh + st * STAGE_H;
            __half* bs = as + A_TILE_H;
            if (part < 2) {
                int c = tid + part * 512;
                int r = c >> 3, seg = (c & 7) * 8;
                cp_async16((uint32_t)__cvta_generic_to_shared(as + r * LDH + seg),
                           A + (size_t)(bm + r) * K + kt * 64 + seg);
            } else {
                int c = tid + (part - 2) * 512;
                int r = c >> 3, seg = (c & 7) * 8;
                cp_async16((uint32_t)__cvta_generic_to_shared(bs + r * LDH + seg),
                           Wt + (size_t)(bn + r) * K + kt * 64 + seg);
            }
        };
        auto load_tile = [&](int kt, int st) {
            #pragma unroll
            for (int i = 0; i < 6; i++) load_chunk(kt, st, i);
        };

        const int KT = K / 64;
        load_tile(0, 0);
        cp_commit();
        load_tile(1, 1);
        cp_commit();

        const int a_row  = wm * 64 + (lane & 15);
        const int a_koff = (lane >> 4) * 8;
        const int b_g = lane >> 3;
        const int b_r = lane & 7;

        for (int kt = 0; kt < KT; kt++) {
            if (kt + 1 < KT) cp_wait1(); else cp_wait0();
            __syncthreads();
            const bool pf = (kt + 2 < KT);
            const int pfs = (kt + 2) % GEMM_STAGES;

            const __half* as = smh + (kt % GEMM_STAGES) * STAGE_H;
            const __half* bs = as + A_TILE_H;
            #pragma unroll
            for (int ks = 0; ks < 4; ks++) {
                if (pf) {
                    if (ks < 2) load_chunk(kt + 2, pfs, ks);      // A parts 0,1
                    load_chunk(kt + 2, pfs, 2 + ks);              // B parts 2..5
                }
                uint32_t a[4][4];
                #pragma unroll
                for (int mt = 0; mt < 4; mt++) {
                    uint32_t addr = (uint32_t)__cvta_generic_to_shared(
                        as + (a_row + mt * 16) * LDH + ks * 16 + a_koff);
                    ldsm_x4(a[mt][0], a[mt][1], a[mt][2], a[mt][3], addr);
                }
                uint32_t b[4][2];
                #pragma unroll
                for (int c = 0; c < 2; c++) {
                    int row = wn * 32 + (2 * c + (b_g >> 1)) * 8 + b_r;
                    int col = ks * 16 + (b_g & 1) * 8;
                    uint32_t addr = (uint32_t)__cvta_generic_to_shared(
                        bs + row * LDH + col);
                    ldsm_x4(b[2 * c][0], b[2 * c][1], b[2 * c + 1][0], b[2 * c + 1][1], addr);
                }
                #pragma unroll
                for (int mt = 0; mt < 4; mt++)
                    #pragma unroll
                    for (int nt = 0; nt < 4; nt++)
                        mma_f16(acc[mt][nt], a[mt], b[nt]);
            }
            if (pf) cp_commit();
        }
    }

    // Epilogue
    const int e_row = bm + wm * 64 + (lane >> 2);
    const int e_col = bn + wn * 32 + (lane & 3) * 2;
    #pragma unroll
    for (int mt = 0; mt < 4; mt++) {
        #pragma unroll
        for (int nt = 0; nt < 4; nt++) {
            const int col = e_col + nt * 8;
            const float bz0 = bias[col], bz1 = bias[col + 1];
            #pragma unroll
            for (int half_i = 0; half_i < 2; half_i++) {
                const int row = e_row + mt * 16 + half_i * 8;
                float v0 = acc[mt][nt][half_i * 2 + 0] + bz0;
                float v1 = acc[mt][nt][half_i * 2 + 1] + bz1;
                if (ACT == 1) {
                    v0 = gelu_fast(v0);
                    v1 = gelu_fast(v1);
                }
                if (ACT == 2) {
                    const float2 r2 = *(const float2*)(res + (size_t)row * N + col);
                    v0 += r2.x; v1 += r2.y;
                    float2 o; o.x = v0; o.y = v1;
                    *(float2*)((float*)C + (size_t)row * N + col) = o;
                } else {
                    __half2 h = __floats2half2_rn(v0, v1);
                    *(uint32_t*)((__half*)C + (size_t)row * N + col) = *(uint32_t*)&h;
                }
            }
        }
    }
}

// ---------------------------------------------------------------------------
// FP16 tensor-core attention with hard threshold (base-2 softmax algebra).
//   out_row = (1/Z > 0.5) ? (xn[j*] @ Wv + bv)/Z : 0   (V computed on demand)
// ---------------------------------------------------------------------------
__global__ __launch_bounds__(256, 3)
void attn_mma_kernel(const __half* __restrict__ qk,
                     const __half* __restrict__ xn,
                     const __half* __restrict__ wt,     // full qkv Wt[3C][C]
                     const float* __restrict__ qkv_b,
                     __half* __restrict__ out,
                     int* __restrict__ flags) {
    extern __shared__ __half smh[];
    __half* Qs = smh;                 // [64][LDH]
    __half* Ks = smh + ATTN_Q_H;      // [2 buf][128][LDH]

    __shared__ float part_m[64][4];
    __shared__ float part_z[64][4];
    __shared__ int   part_j[64][4];
    __shared__ float rscale[64];
    __shared__ int   rjmax[64];
    __shared__ int   s_any;

    const int bh = blockIdx.y;
    const int b  = bh >> 4;
    const int h  = bh & 15;
    const int r0 = blockIdx.x * 64;
    const int tid = threadIdx.x, lane = tid & 31, warp = tid >> 5;
    const int wm = warp >> 2, wn = warp & 3;

    if (tid == 0) s_any = 0;

    #pragma unroll
    for (int i = 0; i < 2; i++) {
        int c = tid + i * 256;
        int r = c >> 3, seg = (c & 7) * 8;
        const __half* src = qk + (size_t)(b * NSEQ + r0 + r) * 2 * CDIM
                            + h * HDIM + seg;
        cp_async16((uint32_t)__cvta_generic_to_shared(Qs + r * LDH + seg), src);
    }

    auto load_k = [&](int c0, int buf) {
        __half* base = Ks + buf * (128 * LDH);
        #pragma unroll
        for (int i = 0; i < 4; i++) {
            int c = tid + i * 256;
            int r = c >> 3, seg = (c & 7) * 8;
            const __half* src = qk + (size_t)(b * NSEQ + c0 + r) * 2 * CDIM
                                + CDIM + h * HDIM + seg;
            cp_async16((uint32_t)__cvta_generic_to_shared(base + r * LDH + seg), src);
        }
    };

    cp_commit();                 // Q group
    load_k(0, 0);
    cp_commit();

    float m_[4], Z_[4];
    int j_[4];
    #pragma unroll
    for (int i = 0; i < 4; i++) { m_[i] = -1e30f; Z_[i] = 0.f; j_[i] = 0; }

    const int b_g = lane >> 3;
    const int b_r = lane & 7;

    for (int kc = 0; kc < 8; kc++) {
        const int buf = kc & 1;
        cp_wait0();
        __syncthreads();
        if (kc < 7) { load_k((kc + 1) * 128, buf ^ 1); cp_commit(); }

        float acc[2][4][4];
        #pragma unroll
        for (int i = 0; i < 2; i++)
            #pragma unroll
            for (int j = 0; j < 4; j++)
                #pragma unroll
                for (int t = 0; t < 4; t++) acc[i][j][t] = 0.f;

        const __half* kb = Ks + buf * (128 * LDH);
        #pragma unroll
        for (int ks = 0; ks < 4; ks++) {
            uint32_t a[2][4];
            #pragma unroll
            for (int mt = 0; mt < 2; mt++) {
                uint32_t addr = (uint32_t)__cvta_generic_to_shared(
                    Qs + (wm * 32 + mt * 16 + (lane & 15)) * LDH
                       + ks * 16 + (lane >> 4) * 8);
                ldsm_x4(a[mt][0], a[mt][1], a[mt][2], a[mt][3], addr);
            }
            uint32_t bfr[4][2];
            #pragma unroll
            for (int c = 0; c < 2; c++) {
                int row = wn * 32 + (2 * c + (b_g >> 1)) * 8 + b_r;
                int col = ks * 16 + (b_g & 1) * 8;
                uint32_t addr = (uint32_t)__cvta_generic_to_shared(
                    kb + row * LDH + col);
                ldsm_x4(bfr[2 * c][0], bfr[2 * c][1], bfr[2 * c + 1][0], bfr[2 * c + 1][1], addr);
            }
            #pragma unroll
            for (int mt = 0; mt < 2; mt++)
                #pragma unroll
                for (int nt = 0; nt < 4; nt++)
                    mma_f16(acc[mt][nt], a[mt], bfr[nt]);
        }

        #pragma unroll
        for (int mt = 0; mt < 2; mt++) {
            #pragma unroll
            for (int half_i = 0; half_i < 2; half_i++) {
                const int si = mt * 2 + half_i;
                const int bcol = kc * 128 + wn * 32 + (lane & 3) * 2;
                float v[8];
                #pragma unroll
                for (int nt = 0; nt < 4; nt++) {
                    v[nt * 2 + 0] = acc[mt][nt][half_i * 2 + 0] * ATT_SCALE_LOG2E;
                    v[nt * 2 + 1] = acc[mt][nt][half_i * 2 + 1] * ATT_SCALE_LOG2E;
                }
                float m01 = fmaxf(v[0], v[1]), m23 = fmaxf(v[2], v[3]);
                float m45 = fmaxf(v[4], v[5]), m67 = fmaxf(v[6], v[7]);
                float cmax = fmaxf(fmaxf(m01, m23), fmaxf(m45, m67));
                if (cmax > m_[si]) {
                    int cj = bcol;
                    #pragma unroll
                    for (int q = 1; q < 8; q++)
                        if (v[q] == cmax) cj = bcol + (q >> 1) * 8 + (q & 1);
                    Z_[si] *= ex2(m_[si] - cmax);
                    m_[si] = cmax;
                    j_[si] = cj;
                }
                float e = 0.f;
                #pragma unroll
                for (int q = 0; q < 8; q++) e += ex2(v[q] - m_[si]);
                Z_[si] += e;
            }
        }
    }

    #pragma unroll
    for (int si = 0; si < 4; si++) {
        float mm = m_[si], zz = Z_[si];
        int jj = j_[si];
        #pragma unroll
        for (int o = 1; o <= 2; o <<= 1) {
            float om = __shfl_xor_sync(0xffffffffu, mm, o);
            float oz = __shfl_xor_sync(0xffffffffu, zz, o);
            int   oj = __shfl_xor_sync(0xffffffffu, jj, o);
            if (om > mm) { zz = zz * ex2(mm - om) + oz; mm = om; jj = oj; }
            else         { zz = zz + oz * ex2(om - mm); }
        }
        if ((lane & 3) == 0) {
            int row = wm * 32 + (si >> 1) * 16 + (si & 1) * 8 + (lane >> 2);
            part_m[row][wn] = mm;
            part_z[row][wn] = zz;
            part_j[row][wn] = jj;
        }
    }
    __syncthreads();

    if (tid < 64) {
        float mm = part_m[tid][0], zz = part_z[tid][0];
        int jj = part_j[tid][0];
        #pragma unroll
        for (int t = 1; t < 4; t++) {
            float om = part_m[tid][t], oz = part_z[tid][t];
            int   oj = part_j[tid][t];
            if (om > mm) { zz = zz * ex2(mm - om) + oz; mm = om; jj = oj; }
            else         { zz = zz + oz * ex2(om - mm); }
        }
        const float amax = 1.0f / zz;
        const float sc = (amax > 0.5f) ? amax : 0.0f;
        rscale[tid] = sc;
        rjmax[tid]  = jj;
        if (sc != 0.0f) s_any = 1;
    }
    __syncthreads();

    if (tid == 0 && s_any) {
        atomicOr(&flags[(b * NSEQ + r0) >> 7], 1);
        atomicOr(&flags[NFLAGS - 1], 1);          // per-layer anyWinner
    }

    const int r  = tid >> 2;
    const int d0 = (tid & 3) * 16;
    const float sc = rscale[r];
    const int jj = rjmax[r];
    __half* orow = out + (size_t)(b * NSEQ + r0 + r) * CDIM + h * HDIM;
    if (sc != 0.0f) {
        const __half* xrow = xn + (size_t)(b * NSEQ + jj) * CDIM;
        #pragma unroll 1
        for (int d = d0; d < d0 + 16; d++) {
            const __half* wrow = wt + (size_t)(2 * CDIM + h * HDIM + d) * CDIM;
            float accv = 0.f;
            const __half2* xp = (const __half2*)xrow;
            const __half2* wp = (const __half2*)wrow;
            #pragma unroll 8
            for (int k2 = 0; k2 < CDIM / 2; k2++) {
                float2 xf = __half22float2(xp[k2]);
                float2 wf = __half22float2(wp[k2]);
                accv += xf.x * wf.x + xf.y * wf.y;
            }
            accv += qkv_b[2 * CDIM + h * HDIM + d];
            orow[d] = __float2half(accv * sc);
        }
    } else {
        uint4 z; z.x = 0u; z.y = 0u; z.z = 0u; z.w = 0u;
        *(uint4*)(orow + d0) = z;
        *(uint4*)(orow + d0 + 8) = z;
    }
}

// ---------------------------------------------------------------------------
extern "C" void kernel_launch(void* const* d_in, const int* in_sizes, int n_in,
                              void* d_out, int out_size) {
    (void)in_sizes; (void)n_in; (void)out_size;
    const float* x      = (const float*)d_in[0];
    const float* pos    = (const float*)d_in[1];
    const float* qkv_w  = (const float*)d_in[2];
    const float* qkv_b  = (const float*)d_in[3];
    const float* proj_w = (const float*)d_in[4];
    const float* proj_b = (const float*)d_in[5];
    const float* ln1_g  = (const float*)d_in[6];
    const float* ln1_b  = (const float*)d_in[7];
    const float* ln2_g  = (const float*)d_in[8];
    const float* ln2_b  = (const float*)d_in[9];
    const float* fc1_w  = (const float*)d_in[10];
    const float* fc1_b  = (const float*)d_in[11];
    const float* fc2_w  = (const float*)d_in[12];
    const float* fc2_b  = (const float*)d_in[13];
    float* out = (float*)d_out;

    __half *xn, *qk, *attn, *ff, *wq, *wp, *w1, *w2;
    int *flags, *pbz, *lneq;
    cudaGetSymbolAddress((void**)&xn,   g_xn);
    cudaGetSymbolAddress((void**)&qk,   g_qk);
    cudaGetSymbolAddress((void**)&attn, g_attn);
    cudaGetSymbolAddress((void**)&ff,   g_ff);
    cudaGetSymbolAddress((void**)&wq,   g_wq);
    cudaGetSymbolAddress((void**)&wp,   g_wp);
    cudaGetSymbolAddress((void**)&w1,   g_w1);
    cudaGetSymbolAddress((void**)&w2,   g_w2);
    cudaGetSymbolAddress((void**)&flags, g_flags);
    cudaGetSymbolAddress((void**)&pbz,  g_pbz);
    cudaGetSymbolAddress((void**)&lneq, g_lneq);

    cudaFuncSetAttribute(hgemm_kernel<1, __half>,
                         cudaFuncAttributeMaxDynamicSharedMemorySize, GEMM_SMEM_BYTES);
    cudaFuncSetAttribute(hgemm_kernel<2, float>,
                         cudaFuncAttributeMaxDynamicSharedMemorySize, GEMM_SMEM_BYTES);
    cudaFuncSetAttribute(hgemm_kernel<3, __half>,
                         cudaFuncAttributeMaxDynamicSharedMemorySize, GEMM_SMEM_BYTES);
    cudaFuncSetAttribute(attn_mma_kernel,
                         cudaFuncAttributeMaxDynamicSharedMemorySize, ATTN_SMEM_BYTES);

    // weight prep: fp16 convert + transpose [K,N] -> [N,K] (once per launch)
    prep_w_kernel<<<dim3(3 * CDIM / 64, CDIM / 64, LAYERS), 256>>>(qkv_w,  wq, CDIM, 3 * CDIM);
    prep_w_kernel<<<dim3(CDIM / 64,     CDIM / 64, LAYERS), 256>>>(proj_w, wp, CDIM, CDIM);
    prep_w_kernel<<<dim3(FFD / 64,      CDIM / 64, LAYERS), 256>>>(fc1_w,  w1, CDIM, FFD);
    prep_w_kernel<<<dim3(CDIM / 64,     FFD / 64,  LAYERS), 256>>>(fc2_w,  w2, FFD, CDIM);
    smallprep_kernel<<<LAYERS, 256>>>(proj_b, ln1_g, ln1_b, ln2_g, ln2_b, pbz, lneq);

    for (int l = 0; l < LAYERS; l++) {
        const __half* wql = wq + (size_t)l * CDIM * 3 * CDIM;
        // --- attention block ---
        if (l == 0) {
            // fused: out = x + pos;  xn = LN(out)
            ln_kernel<<<TOK / 8, 256>>>(x, pos, out,
                                        ln1_g, ln1_b, xn, flags, nullptr, nullptr);
        } else {
            ln_kernel<<<TOK / 8, 256>>>(out, nullptr, nullptr,
                                        ln1_g + (size_t)l * CDIM,
                                        ln1_b + (size_t)l * CDIM, xn, flags,
                                        nullptr, nullptr);
        }
        // Q,K only (Wt rows 0..2C): N = 2048
        hgemm_kernel<3, __half><<<dim3(2 * CDIM / 256, TOK / 128), 512, GEMM_SMEM_BYTES>>>(
            xn, wql, qkv_b + (size_t)l * 3 * CDIM,
            nullptr, qk, TOK, 2 * CDIM, CDIM, nullptr, nullptr);
        attn_mma_kernel<<<dim3(NSEQ / 64, BSZ * HEADS), 256, ATTN_SMEM_BYTES>>>(
            qk, xn, wql, qkv_b + (size_t)l * 3 * CDIM, attn, flags);
        hgemm_kernel<2, float><<<dim3(CDIM / 256, TOK / 128), 512, GEMM_SMEM_BYTES>>>(
            attn, wp + (size_t)l * CDIM * CDIM, proj_b + (size_t)l * CDIM,
            out, out, TOK, CDIM, CDIM, flags, pbz + l);
        // --- MLP block ---
        ln_kernel<<<TOK / 8, 256>>>(out, nullptr, nullptr,
                                    ln2_g + (size_t)l * CDIM,
                                    ln2_b + (size_t)l * CDIM, xn, nullptr,
                                    flags + NFLAGS - 1, lneq + l);
        hgemm_kernel<1, __half><<<dim3(FFD / 256, TOK / 128), 512, GEMM_SMEM_BYTES>>>(
            xn, w1 + (size_t)l * CDIM * FFD, fc1_b + (size_t)l * FFD,
            nullptr, ff, TOK, FFD, CDIM, nullptr, nullptr);
        hgemm_kernel<2, float><<<dim3(CDIM / 256, TOK / 128), 512, GEMM_SMEM_BYTES>>>(
            ff, w2 + (size_t)l * FFD * CDIM, fc2_b + (size_t)l * CDIM,
            out, out, TOK, CDIM, FFD, nullptr, nullptr);
    }
}

// round 14
// speedup vs baseline: 1.0592x; 1.0592x over previous
#include <cuda_runtime.h>
#include <cuda_fp16.h>
#include <math.h>
#include <stdint.h>

#define TOK   4096          // B*N
#define BSZ   4
#define NSEQ  1024
#define CDIM  1024
#define HEADS 16
#define HDIM  64
#define FFD   4096
#define LAYERS 4
#define ATT_SCALE_LOG2E 0.1803368801111244f   // 64^-0.5 * log2(e)
#define NFLAGS (TOK / 128 + 1)                // [0..31] tile flags, [32] anyWinner

// GEMM smem strides (halves)
#define LDH 72              // 64 halves + 8 pad -> 144 B row stride
#define GEMM_TILE_H (128 * LDH)                 // halves per (A or B) tile
#define STAGE_H (2 * GEMM_TILE_H)               // A + B per stage
#define GEMM_STAGES 3
#define GEMM_SMEM_BYTES (GEMM_STAGES * STAGE_H * 2)   // 110592 B

// attn smem: Q [64][72] + K [2 buf][128][72] halves
#define ATTN_Q_H (64 * LDH)
#define ATTN_K_H (2 * 128 * LDH)
#define ATTN_SMEM_BYTES ((ATTN_Q_H + ATTN_K_H) * 2)

// Scratch (device globals; no allocation allowed)
__device__ __half g_xn  [(size_t)TOK * CDIM];
__device__ __half g_qk  [(size_t)TOK * 2 * CDIM];   // [tok][Q(0..C) K(C..2C)]
__device__ __half g_attn[(size_t)TOK * CDIM];
__device__ __half g_ff  [(size_t)TOK * FFD];
__device__ int    g_flags[NFLAGS];
__device__ int    g_pbz[LAYERS];                    // proj bias nonzero
__device__ int    g_lneq[LAYERS];                   // ln1 params == ln2 params
// fp16, TRANSPOSED weights: Wt[N][K]
__device__ __half g_wq[(size_t)LAYERS * CDIM * 3 * CDIM];
__device__ __half g_wp[(size_t)LAYERS * CDIM * CDIM];
__device__ __half g_w1[(size_t)LAYERS * CDIM * FFD];
__device__ __half g_w2[(size_t)LAYERS * FFD * CDIM];

// ---------------------------------------------------------------------------
__device__ __forceinline__ void cp_async16(uint32_t s, const void* g) {
    asm volatile("cp.async.cg.shared.global [%0], [%1], 16;" :: "r"(s), "l"(g));
}
__device__ __forceinline__ void cp_commit() {
    asm volatile("cp.async.commit_group;");
}
__device__ __forceinline__ void cp_wait0() {
    asm volatile("cp.async.wait_group 0;");
}
__device__ __forceinline__ void cp_wait1() {
    asm volatile("cp.async.wait_group 1;");
}
__device__ __forceinline__ void ldsm_x4(uint32_t& r0, uint32_t& r1, uint32_t& r2,
                                        uint32_t& r3, uint32_t addr) {
    asm volatile("ldmatrix.sync.aligned.m8n8.x4.shared.b16 {%0,%1,%2,%3}, [%4];"
                 : "=r"(r0), "=r"(r1), "=r"(r2), "=r"(r3) : "r"(addr));
}
__device__ __forceinline__ void mma_f16(float* c, const uint32_t* a, const uint32_t* b) {
    asm volatile(
        "mma.sync.aligned.m16n8k16.row.col.f32.f16.f16.f32 "
        "{%0,%1,%2,%3}, {%4,%5,%6,%7}, {%8,%9}, {%0,%1,%2,%3};"
        : "+f"(c[0]), "+f"(c[1]), "+f"(c[2]), "+f"(c[3])
        : "r"(a[0]), "r"(a[1]), "r"(a[2]), "r"(a[3]), "r"(b[0]), "r"(b[1]));
}
__device__ __forceinline__ float tanh_fast(float x) {
    float y;
    asm("tanh.approx.f32 %0, %1;" : "=f"(y) : "f"(x));
    return y;
}
__device__ __forceinline__ float gelu_fast(float v) {
    const float c0 = 0.7978845608028654f, c1 = 0.044715f;
    return 0.5f * v * (1.0f + tanh_fast(c0 * (v + c1 * v * v * v)));
}
__device__ __forceinline__ float ex2(float x) {   // 2^x, HW MUFU
    float y;
    asm("ex2.approx.f32 %0, %1;" : "=f"(y) : "f"(x));
    return y;
}

// ---------------------------------------------------------------------------
// weight prep: fp32 [K,N] -> half [N,K] (transpose + convert), per-layer via z
// ---------------------------------------------------------------------------
__global__ __launch_bounds__(256)
void prep_w_kernel(const float* __restrict__ src,
                   __half* __restrict__ dst, int K, int N) {
    __shared__ __half t[64][65];
    const size_t lo = (size_t)blockIdx.z * K * N;
    const int n0 = blockIdx.x * 64, k0 = blockIdx.y * 64;
    const int tx = threadIdx.x & 15, ty = threadIdx.x >> 4;   // 16x16

    #pragma unroll
    for (int ii = 0; ii < 4; ii++) {
        const int k = k0 + ty + ii * 16;
        const float4 v = *(const float4*)&src[lo + (size_t)k * N + n0 + tx * 4];
        t[tx * 4 + 0][ty + ii * 16] = __float2half(v.x);
        t[tx * 4 + 1][ty + ii * 16] = __float2half(v.y);
        t[tx * 4 + 2][ty + ii * 16] = __float2half(v.z);
        t[tx * 4 + 3][ty + ii * 16] = __float2half(v.w);
    }
    __syncthreads();

    const int w = threadIdx.x >> 5, l = threadIdx.x & 31;
    #pragma unroll
    for (int r = 0; r < 8; r++) {
        const int n = w * 8 + r;
        __half2 h = __halves2half2(t[n][2 * l], t[n][2 * l + 1]);
        *(uint32_t*)&dst[lo + (size_t)(n0 + n) * K + k0 + 2 * l] = *(uint32_t*)&h;
    }
}

// ---------------------------------------------------------------------------
// small per-layer checks: proj bias nonzero? ln1 params == ln2 params?
// ---------------------------------------------------------------------------
__global__ void smallprep_kernel(const float* __restrict__ proj_b,
                                 const float* __restrict__ l1g,
                                 const float* __restrict__ l1b,
                                 const float* __restrict__ l2g,
                                 const float* __restrict__ l2b,
                                 int* __restrict__ pbz,
                                 int* __restrict__ lneq) {
    const int l = blockIdx.x;
    const size_t o = (size_t)l * CDIM;
    int nz = 0, neq = 0;
    for (int i = threadIdx.x; i < CDIM; i += 256) {
        nz  |= (proj_b[o + i] != 0.0f);
        neq |= (l1g[o + i] != l2g[o + i]) | (l1b[o + i] != l2b[o + i]);
    }
    nz  = __syncthreads_or(nz);
    neq = __syncthreads_or(neq);
    if (threadIdx.x == 0) { pbz[l] = nz; lneq[l] = !neq; }
}

// ---------------------------------------------------------------------------
// LayerNorm (generic): ONE WARP per row. fp32 in -> fp16 out.
// If `pos` non-null (first layer): in = x, adds pos, ALSO writes fp32 x+pos
// to `resout` (residual stream init) — fuses add_pos.
// If `flags` given (ln1), block 0 zeroes all flags (incl. anyWinner).
// If `anyw`/`lneq` given (ln2), early-exit when attention was an identity and
// ln params match ln1 (xn already holds the correct values).
// ---------------------------------------------------------------------------
__global__ __launch_bounds__(256)
void ln_kernel(const float* __restrict__ in,
               const float* __restrict__ pos,
               float* __restrict__ resout,
               const float* __restrict__ g,
               const float* __restrict__ b,
               __half* __restrict__ out,
               int* __restrict__ flags,
               const int* __restrict__ anyw,
               const int* __restrict__ lneq) {
    if (anyw && lneq && lneq[0] != 0 && anyw[0] == 0) return;
    if (flags && blockIdx.x == 0 && threadIdx.x < NFLAGS) flags[threadIdx.x] = 0;

    const int row  = blockIdx.x * 8 + (threadIdx.x >> 5);
    const int lane = threadIdx.x & 31;
    const float4* rp = (const float4*)(in + (size_t)row * CDIM);
    const float4* pp = pos ? (const float4*)(pos + (size_t)(row & (NSEQ - 1)) * CDIM)
                           : nullptr;
    float4* ro = resout ? (float4*)(resout + (size_t)row * CDIM) : nullptr;

    float4 xv[8];
    float s = 0.f, sq = 0.f;
    #pragma unroll
    for (int i = 0; i < 8; i++) {
        xv[i] = rp[i * 32 + lane];
        if (pos) {
            const float4 p = pp[i * 32 + lane];
            xv[i].x += p.x; xv[i].y += p.y; xv[i].z += p.z; xv[i].w += p.w;
            ro[i * 32 + lane] = xv[i];
        }
        s  += xv[i].x + xv[i].y + xv[i].z + xv[i].w;
        sq += xv[i].x * xv[i].x + xv[i].y * xv[i].y
            + xv[i].z * xv[i].z + xv[i].w * xv[i].w;
    }
    #pragma unroll
    for (int o = 16; o > 0; o >>= 1) {
        s  += __shfl_xor_sync(0xffffffffu, s, o);
        sq += __shfl_xor_sync(0xffffffffu, sq, o);
    }
    const float mean = s * (1.0f / CDIM);
    const float var  = sq * (1.0f / CDIM) - mean * mean;
    const float rstd = rsqrtf(var + 1e-5f);

    const float4* gp = (const float4*)g;
    const float4* bp = (const float4*)b;
    uint2* op = (uint2*)(out + (size_t)row * CDIM);
    #pragma unroll
    for (int i = 0; i < 8; i++) {
        const float4 gg = gp[i * 32 + lane];
        const float4 bb = bp[i * 32 + lane];
        __half2 h0 = __floats2half2_rn((xv[i].x - mean) * rstd * gg.x + bb.x,
                                       (xv[i].y - mean) * rstd * gg.y + bb.y);
        __half2 h1 = __floats2half2_rn((xv[i].z - mean) * rstd * gg.z + bb.z,
                                       (xv[i].w - mean) * rstd * gg.w + bb.w);
        uint2 o;
        o.x = *(uint32_t*)&h0;
        o.y = *(uint32_t*)&h1;
        op[i * 32 + lane] = o;
    }
}

// ---------------------------------------------------------------------------
// FP16 tensor-core GEMM: C = A[M,K] @ Wt[N,K]^T + bias
// 128x128 CTA tile, BK=64, 256 threads, 3-stage cp.async pipeline with the
// next-next tile's loads interleaved into the MMA ks-loop (no LSU burst).
// ACT 1: gelu (half out), 2: +residual (fp32 out; tile-skip via flags and
//        full early-exit when bias is known-zero), 3: plain (half out)
// ---------------------------------------------------------------------------
template <int ACT, typename OUT_T>
__global__ __launch_bounds__(256, 2)
void hgemm_kernel(const __half* __restrict__ A,
                  const __half* __restrict__ Wt,
                  const float* __restrict__ bias,
                  const float* __restrict__ res,
                  OUT_T* __restrict__ C,
                  int M, int N, int K,
                  const int* __restrict__ flags,
                  const int* __restrict__ bias_nz) {
    extern __shared__ __half smh[];

    const int tid  = threadIdx.x;
    const int lane = tid & 31;
    const int warp = tid >> 5;
    const int wm = warp >> 2;
    const int wn = warp & 3;
    const int bm = blockIdx.y * 128;
    const int bn = blockIdx.x * 128;

    const bool skip = (ACT == 2) && flags && (flags[blockIdx.y] == 0);
    if (ACT == 2 && skip && bias_nz && bias_nz[0] == 0) return;  // out += 0

    float acc[4][4][4];
    #pragma unroll
    for (int i = 0; i < 4; i++)
        #pragma unroll
        for (int j = 0; j < 4; j++)
            #pragma unroll
            for (int t = 0; t < 4; t++) acc[i][j][t] = 0.f;

    if (!skip) {
        // one 16B A-chunk + one 16B B-chunk per thread per part (4 parts/tile)
        auto load_chunk = [&](int kt, int st, int part) {
            const __half* Ag = A  + (size_t)bm * K + kt * 64;
            const __half* Bg = Wt + (size_t)bn * K + kt * 64;
            __half* as = smh + st * STAGE_H;
            __half* bs = as + GEMM_TILE_H;
            int c = tid + part * 256;
            int r = c >> 3, seg = (c & 7) * 8;
            cp_async16((uint32_t)__cvta_generic_to_shared(as + r * LDH + seg),
                       Ag + (size_t)r * K + seg);
            cp_async16((uint32_t)__cvta_generic_to_shared(bs + r * LDH + seg),
                       Bg + (size_t)r * K + seg);
        };
        auto load_tile = [&](int kt, int st) {
            #pragma unroll
            for (int i = 0; i < 4; i++) load_chunk(kt, st, i);
        };

        const int KT = K / 64;
        load_tile(0, 0);
        cp_commit();
        load_tile(1, 1);
        cp_commit();

        const int a_row  = wm * 64 + (lane & 15);
        const int a_koff = (lane >> 4) * 8;
        const int b_g = lane >> 3;
        const int b_r = lane & 7;

        for (int kt = 0; kt < KT; kt++) {
            if (kt + 1 < KT) cp_wait1(); else cp_wait0();
            __syncthreads();
            const bool pf = (kt + 2 < KT);
            const int pfs = (kt + 2) % GEMM_STAGES;

            const __half* as = smh + (kt % GEMM_STAGES) * STAGE_H;
            const __half* bs = as + GEMM_TILE_H;
            #pragma unroll
            for (int ks = 0; ks < 4; ks++) {
                if (pf) load_chunk(kt + 2, pfs, ks);
                uint32_t a[4][4];
                #pragma unroll
                for (int mt = 0; mt < 4; mt++) {
                    uint32_t addr = (uint32_t)__cvta_generic_to_shared(
                        as + (a_row + mt * 16) * LDH + ks * 16 + a_koff);
                    ldsm_x4(a[mt][0], a[mt][1], a[mt][2], a[mt][3], addr);
                }
                uint32_t b[4][2];
                #pragma unroll
                for (int c = 0; c < 2; c++) {
                    int row = wn * 32 + (2 * c + (b_g >> 1)) * 8 + b_r;
                    int col = ks * 16 + (b_g & 1) * 8;
                    uint32_t addr = (uint32_t)__cvta_generic_to_shared(
                        bs + row * LDH + col);
                    ldsm_x4(b[2 * c][0], b[2 * c][1], b[2 * c + 1][0], b[2 * c + 1][1], addr);
                }
                #pragma unroll
                for (int mt = 0; mt < 4; mt++)
                    #pragma unroll
                    for (int nt = 0; nt < 4; nt++)
                        mma_f16(acc[mt][nt], a[mt], b[nt]);
            }
            if (pf) cp_commit();
        }
    }

    // Epilogue
    const int e_row = bm + wm * 64 + (lane >> 2);
    const int e_col = bn + wn * 32 + (lane & 3) * 2;
    #pragma unroll
    for (int mt = 0; mt < 4; mt++) {
        #pragma unroll
        for (int nt = 0; nt < 4; nt++) {
            const int col = e_col + nt * 8;
            const float bz0 = bias[col], bz1 = bias[col + 1];
            #pragma unroll
            for (int half_i = 0; half_i < 2; half_i++) {
                const int row = e_row + mt * 16 + half_i * 8;
                float v0 = acc[mt][nt][half_i * 2 + 0] + bz0;
                float v1 = acc[mt][nt][half_i * 2 + 1] + bz1;
                if (ACT == 1) {
                    v0 = gelu_fast(v0);
                    v1 = gelu_fast(v1);
                }
                if (ACT == 2) {
                    const float2 r2 = *(const float2*)(res + (size_t)row * N + col);
                    v0 += r2.x; v1 += r2.y;
                    float2 o; o.x = v0; o.y = v1;
                    *(float2*)((float*)C + (size_t)row * N + col) = o;
                } else {
                    __half2 h = __floats2half2_rn(v0, v1);
                    *(uint32_t*)((__half*)C + (size_t)row * N + col) = *(uint32_t*)&h;
                }
            }
        }
    }
}

// ---------------------------------------------------------------------------
// FP16 tensor-core attention with hard threshold (base-2 softmax algebra).
//   out_row = (1/Z > 0.5) ? (xn[j*] @ Wv + bv)/Z : 0   (V computed on demand)
// ---------------------------------------------------------------------------
__global__ __launch_bounds__(256, 3)
void attn_mma_kernel(const __half* __restrict__ qk,
                     const __half* __restrict__ xn,
                     const __half* __restrict__ wt,     // full qkv Wt[3C][C]
                     const float* __restrict__ qkv_b,
                     __half* __restrict__ out,
                     int* __restrict__ flags) {
    extern __shared__ __half smh[];
    __half* Qs = smh;                 // [64][LDH]
    __half* Ks = smh + ATTN_Q_H;      // [2 buf][128][LDH]

    __shared__ float part_m[64][4];
    __shared__ float part_z[64][4];
    __shared__ int   part_j[64][4];
    __shared__ float rscale[64];
    __shared__ int   rjmax[64];
    __shared__ int   s_any;

    const int bh = blockIdx.y;
    const int b  = bh >> 4;
    const int h  = bh & 15;
    const int r0 = blockIdx.x * 64;
    const int tid = threadIdx.x, lane = tid & 31, warp = tid >> 5;
    const int wm = warp >> 2, wn = warp & 3;

    if (tid == 0) s_any = 0;

    #pragma unroll
    for (int i = 0; i < 2; i++) {
        int c = tid + i * 256;
        int r = c >> 3, seg = (c & 7) * 8;
        const __half* src = qk + (size_t)(b * NSEQ + r0 + r) * 2 * CDIM
                            + h * HDIM + seg;
        cp_async16((uint32_t)__cvta_generic_to_shared(Qs + r * LDH + seg), src);
    }

    auto load_k = [&](int c0, int buf) {
        __half* base = Ks + buf * (128 * LDH);
        #pragma unroll
        for (int i = 0; i < 4; i++) {
            int c = tid + i * 256;
            int r = c >> 3, seg = (c & 7) * 8;
            const __half* src = qk + (size_t)(b * NSEQ + c0 + r) * 2 * CDIM
                                + CDIM + h * HDIM + seg;
            cp_async16((uint32_t)__cvta_generic_to_shared(base + r * LDH + seg), src);
        }
    };

    cp_commit();                 // Q group
    load_k(0, 0);
    cp_commit();

    float m_[4], Z_[4];
    int j_[4];
    #pragma unroll
    for (int i = 0; i < 4; i++) { m_[i] = -1e30f; Z_[i] = 0.f; j_[i] = 0; }

    const int b_g = lane >> 3;
    const int b_r = lane & 7;

    for (int kc = 0; kc < 8; kc++) {
        const int buf = kc & 1;
        cp_wait0();
        __syncthreads();
        if (kc < 7) { load_k((kc + 1) * 128, buf ^ 1); cp_commit(); }

        float acc[2][4][4];
        #pragma unroll
        for (int i = 0; i < 2; i++)
            #pragma unroll
            for (int j = 0; j < 4; j++)
                #pragma unroll
                for (int t = 0; t < 4; t++) acc[i][j][t] = 0.f;

        const __half* kb = Ks + buf * (128 * LDH);
        #pragma unroll
        for (int ks = 0; ks < 4; ks++) {
            uint32_t a[2][4];
            #pragma unroll
            for (int mt = 0; mt < 2; mt++) {
                uint32_t addr = (uint32_t)__cvta_generic_to_shared(
                    Qs + (wm * 32 + mt * 16 + (lane & 15)) * LDH
                       + ks * 16 + (lane >> 4) * 8);
                ldsm_x4(a[mt][0], a[mt][1], a[mt][2], a[mt][3], addr);
            }
            uint32_t bfr[4][2];
            #pragma unroll
            for (int c = 0; c < 2; c++) {
                int row = wn * 32 + (2 * c + (b_g >> 1)) * 8 + b_r;
                int col = ks * 16 + (b_g & 1) * 8;
                uint32_t addr = (uint32_t)__cvta_generic_to_shared(
                    kb + row * LDH + col);
                ldsm_x4(bfr[2 * c][0], bfr[2 * c][1], bfr[2 * c + 1][0], bfr[2 * c + 1][1], addr);
            }
            #pragma unroll
            for (int mt = 0; mt < 2; mt++)
                #pragma unroll
                for (int nt = 0; nt < 4; nt++)
                    mma_f16(acc[mt][nt], a[mt], bfr[nt]);
        }

        #pragma unroll
        for (int mt = 0; mt < 2; mt++) {
            #pragma unroll
            for (int half_i = 0; half_i < 2; half_i++) {
                const int si = mt * 2 + half_i;
                const int bcol = kc * 128 + wn * 32 + (lane & 3) * 2;
                float v[8];
                #pragma unroll
                for (int nt = 0; nt < 4; nt++) {
                    v[nt * 2 + 0] = acc[mt][nt][half_i * 2 + 0] * ATT_SCALE_LOG2E;
                    v[nt * 2 + 1] = acc[mt][nt][half_i * 2 + 1] * ATT_SCALE_LOG2E;
                }
                float m01 = fmaxf(v[0], v[1]), m23 = fmaxf(v[2], v[3]);
                float m45 = fmaxf(v[4], v[5]), m67 = fmaxf(v[6], v[7]);
                float cmax = fmaxf(fmaxf(m01, m23), fmaxf(m45, m67));
                if (cmax > m_[si]) {
                    int cj = bcol;
                    #pragma unroll
                    for (int q = 1; q < 8; q++)
                        if (v[q] == cmax) cj = bcol + (q >> 1) * 8 + (q & 1);
                    Z_[si] *= ex2(m_[si] - cmax);
                    m_[si] = cmax;
                    j_[si] = cj;
                }
                float e = 0.f;
                #pragma unroll
                for (int q = 0; q < 8; q++) e += ex2(v[q] - m_[si]);
                Z_[si] += e;
            }
        }
    }

    #pragma unroll
    for (int si = 0; si < 4; si++) {
        float mm = m_[si], zz = Z_[si];
        int jj = j_[si];
        #pragma unroll
        for (int o = 1; o <= 2; o <<= 1) {
            float om = __shfl_xor_sync(0xffffffffu, mm, o);
            float oz = __shfl_xor_sync(0xffffffffu, zz, o);
            int   oj = __shfl_xor_sync(0xffffffffu, jj, o);
            if (om > mm) { zz = zz * ex2(mm - om) + oz; mm = om; jj = oj; }
            else         { zz = zz + oz * ex2(om - mm); }
        }
        if ((lane & 3) == 0) {
            int row = wm * 32 + (si >> 1) * 16 + (si & 1) * 8 + (lane >> 2);
            part_m[row][wn] = mm;
            part_z[row][wn] = zz;
            part_j[row][wn] = jj;
        }
    }
    __syncthreads();

    if (tid < 64) {
        float mm = part_m[tid][0], zz = part_z[tid][0];
        int jj = part_j[tid][0];
        #pragma unroll
        for (int t = 1; t < 4; t++) {
            float om = part_m[tid][t], oz = part_z[tid][t];
            int   oj = part_j[tid][t];
            if (om > mm) { zz = zz * ex2(mm - om) + oz; mm = om; jj = oj; }
            else         { zz = zz + oz * ex2(om - mm); }
        }
        const float amax = 1.0f / zz;
        const float sc = (amax > 0.5f) ? amax : 0.0f;
        rscale[tid] = sc;
        rjmax[tid]  = jj;
        if (sc != 0.0f) s_any = 1;
    }
    __syncthreads();

    if (tid == 0 && s_any) {
        atomicOr(&flags[(b * NSEQ + r0) >> 7], 1);
        atomicOr(&flags[NFLAGS - 1], 1);          // per-layer anyWinner
    }

    const int r  = tid >> 2;
    const int d0 = (tid & 3) * 16;
    const float sc = rscale[r];
    const int jj = rjmax[r];
    __half* orow = out + (size_t)(b * NSEQ + r0 + r) * CDIM + h * HDIM;
    if (sc != 0.0f) {
        const __half* xrow = xn + (size_t)(b * NSEQ + jj) * CDIM;
        #pragma unroll 1
        for (int d = d0; d < d0 + 16; d++) {
            const __half* wrow = wt + (size_t)(2 * CDIM + h * HDIM + d) * CDIM;
            float accv = 0.f;
            const __half2* xp = (const __half2*)xrow;
            const __half2* wp = (const __half2*)wrow;
            #pragma unroll 8
            for (int k2 = 0; k2 < CDIM / 2; k2++) {
                float2 xf = __half22float2(xp[k2]);
                float2 wf = __half22float2(wp[k2]);
                accv += xf.x * wf.x + xf.y * wf.y;
            }
            accv += qkv_b[2 * CDIM + h * HDIM + d];
            orow[d] = __float2half(accv * sc);
        }
    } else {
        uint4 z; z.x = 0u; z.y = 0u; z.z = 0u; z.w = 0u;
        *(uint4*)(orow + d0) = z;
        *(uint4*)(orow + d0 + 8) = z;
    }
}

// ---------------------------------------------------------------------------
extern "C" void kernel_launch(void* const* d_in, const int* in_sizes, int n_in,
                              void* d_out, int out_size) {
    (void)in_sizes; (void)n_in; (void)out_size;
    const float* x      = (const float*)d_in[0];
    const float* pos    = (const float*)d_in[1];
    const float* qkv_w  = (const float*)d_in[2];
    const float* qkv_b  = (const float*)d_in[3];
    const float* proj_w = (const float*)d_in[4];
    const float* proj_b = (const float*)d_in[5];
    const float* ln1_g  = (const float*)d_in[6];
    const float* ln1_b  = (const float*)d_in[7];
    const float* ln2_g  = (const float*)d_in[8];
    const float* ln2_b  = (const float*)d_in[9];
    const float* fc1_w  = (const float*)d_in[10];
    const float* fc1_b  = (const float*)d_in[11];
    const float* fc2_w  = (const float*)d_in[12];
    const float* fc2_b  = (const float*)d_in[13];
    float* out = (float*)d_out;

    __half *xn, *qk, *attn, *ff, *wq, *wp, *w1, *w2;
    int *flags, *pbz, *lneq;
    cudaGetSymbolAddress((void**)&xn,   g_xn);
    cudaGetSymbolAddress((void**)&qk,   g_qk);
    cudaGetSymbolAddress((void**)&attn, g_attn);
    cudaGetSymbolAddress((void**)&ff,   g_ff);
    cudaGetSymbolAddress((void**)&wq,   g_wq);
    cudaGetSymbolAddress((void**)&wp,   g_wp);
    cudaGetSymbolAddress((void**)&w1,   g_w1);
    cudaGetSymbolAddress((void**)&w2,   g_w2);
    cudaGetSymbolAddress((void**)&flags, g_flags);
    cudaGetSymbolAddress((void**)&pbz,  g_pbz);
    cudaGetSymbolAddress((void**)&lneq, g_lneq);

    cudaFuncSetAttribute(hgemm_kernel<1, __half>,
                         cudaFuncAttributeMaxDynamicSharedMemorySize, GEMM_SMEM_BYTES);
    cudaFuncSetAttribute(hgemm_kernel<2, float>,
                         cudaFuncAttributeMaxDynamicSharedMemorySize, GEMM_SMEM_BYTES);
    cudaFuncSetAttribute(hgemm_kernel<3, __half>,
                         cudaFuncAttributeMaxDynamicSharedMemorySize, GEMM_SMEM_BYTES);
    cudaFuncSetAttribute(attn_mma_kernel,
                         cudaFuncAttributeMaxDynamicSharedMemorySize, ATTN_SMEM_BYTES);

    // weight prep: fp16 convert + transpose [K,N] -> [N,K] (once per launch)
    prep_w_kernel<<<dim3(3 * CDIM / 64, CDIM / 64, LAYERS), 256>>>(qkv_w,  wq, CDIM, 3 * CDIM);
    prep_w_kernel<<<dim3(CDIM / 64,     CDIM / 64, LAYERS), 256>>>(proj_w, wp, CDIM, CDIM);
    prep_w_kernel<<<dim3(FFD / 64,      CDIM / 64, LAYERS), 256>>>(fc1_w,  w1, CDIM, FFD);
    prep_w_kernel<<<dim3(CDIM / 64,     FFD / 64,  LAYERS), 256>>>(fc2_w,  w2, FFD, CDIM);
    smallprep_kernel<<<LAYERS, 256>>>(proj_b, ln1_g, ln1_b, ln2_g, ln2_b, pbz, lneq);

    for (int l = 0; l < LAYERS; l++) {
        const __half* wql = wq + (size_t)l * CDIM * 3 * CDIM;
        // --- attention block ---
        if (l == 0) {
            // fused: out = x + pos;  xn = LN(out)
            ln_kernel<<<TOK / 8, 256>>>(x, pos, out,
                                        ln1_g, ln1_b, xn, flags, nullptr, nullptr);
        } else {
            ln_kernel<<<TOK / 8, 256>>>(out, nullptr, nullptr,
                                        ln1_g + (size_t)l * CDIM,
                                        ln1_b + (size_t)l * CDIM, xn, flags,
                                        nullptr, nullptr);
        }
        // Q,K only (Wt rows 0..2C): N = 2048
        hgemm_kernel<3, __half><<<dim3(2 * CDIM / 128, TOK / 128), 256, GEMM_SMEM_BYTES>>>(
            xn, wql, qkv_b + (size_t)l * 3 * CDIM,
            nullptr, qk, TOK, 2 * CDIM, CDIM, nullptr, nullptr);
        attn_mma_kernel<<<dim3(NSEQ / 64, BSZ * HEADS), 256, ATTN_SMEM_BYTES>>>(
            qk, xn, wql, qkv_b + (size_t)l * 3 * CDIM, attn, flags);
        hgemm_kernel<2, float><<<dim3(CDIM / 128, TOK / 128), 256, GEMM_SMEM_BYTES>>>(
            attn, wp + (size_t)l * CDIM * CDIM, proj_b + (size_t)l * CDIM,
            out, out, TOK, CDIM, CDIM, flags, pbz + l);
        // --- MLP block ---
        ln_kernel<<<TOK / 8, 256>>>(out, nullptr, nullptr,
                                    ln2_g + (size_t)l * CDIM,
                                    ln2_b + (size_t)l * CDIM, xn, nullptr,
                                    flags + NFLAGS - 1, lneq + l);
        hgemm_kernel<1, __half><<<dim3(FFD / 128, TOK / 128), 256, GEMM_SMEM_BYTES>>>(
            xn, w1 + (size_t)l * CDIM * FFD, fc1_b + (size_t)l * FFD,
            nullptr, ff, TOK, FFD, CDIM, nullptr, nullptr);
        hgemm_kernel<2, float><<<dim3(CDIM / 128, TOK / 128), 256, GEMM_SMEM_BYTES>>>(
            ff, w2 + (size_t)l * FFD * CDIM, fc2_b + (size_t)l * CDIM,
            out, out, TOK, CDIM, FFD, nullptr, nullptr);
    }
}

// round 15
// speedup vs baseline: 1.0742x; 1.0142x over previous
#include <cuda_runtime.h>
#include <cuda_fp16.h>
#include <math.h>
#include <stdint.h>

#define TOK   4096          // B*N
#define BSZ   4
#define NSEQ  1024
#define CDIM  1024
#define HEADS 16
#define HDIM  64
#define FFD   4096
#define LAYERS 4
#define ATT_SCALE_LOG2E 0.1803368801111244f   // 64^-0.5 * log2(e)
#define NFLAGS (TOK / 128 + 1)                // [0..31] tile flags, [32] anyWinner

// GEMM smem strides (halves)
#define LDH 72              // 64 halves + 8 pad -> 144 B row stride
#define GEMM_TILE_H (128 * LDH)                 // halves per (A or B) tile
#define STAGE_H (2 * GEMM_TILE_H)               // A + B per stage
#define GEMM_STAGES 3
#define GEMM_SMEM_BYTES (GEMM_STAGES * STAGE_H * 2)   // 110592 B

// attn smem: Q [64][72] + K [2 buf][128][72] halves
#define ATTN_Q_H (64 * LDH)
#define ATTN_K_H (2 * 128 * LDH)
#define ATTN_SMEM_BYTES ((ATTN_Q_H + ATTN_K_H) * 2)

// Scratch (device globals; no allocation allowed)
__device__ __half g_xn  [(size_t)TOK * CDIM];
__device__ __half g_qk  [(size_t)TOK * 2 * CDIM];   // [tok][Q'(0..C) K(C..2C)]
__device__ __half g_attn[(size_t)TOK * CDIM];
__device__ __half g_ff  [(size_t)TOK * FFD];
__device__ int    g_flags[NFLAGS];
__device__ int    g_pbz[LAYERS];                    // proj bias nonzero
__device__ int    g_lneq[LAYERS];                   // ln1 params == ln2 params
// fp16, TRANSPOSED weights: Wt[N][K]
__device__ __half g_wq[(size_t)LAYERS * CDIM * 3 * CDIM];
__device__ __half g_wp[(size_t)LAYERS * CDIM * CDIM];
__device__ __half g_w1[(size_t)LAYERS * CDIM * FFD];
__device__ __half g_w2[(size_t)LAYERS * FFD * CDIM];

// ---------------------------------------------------------------------------
__device__ __forceinline__ void cp_async16(uint32_t s, const void* g) {
    asm volatile("cp.async.cg.shared.global [%0], [%1], 16;" :: "r"(s), "l"(g));
}
__device__ __forceinline__ void cp_commit() {
    asm volatile("cp.async.commit_group;");
}
__device__ __forceinline__ void cp_wait0() {
    asm volatile("cp.async.wait_group 0;");
}
__device__ __forceinline__ void cp_wait1() {
    asm volatile("cp.async.wait_group 1;");
}
__device__ __forceinline__ void ldsm_x4(uint32_t& r0, uint32_t& r1, uint32_t& r2,
                                        uint32_t& r3, uint32_t addr) {
    asm volatile("ldmatrix.sync.aligned.m8n8.x4.shared.b16 {%0,%1,%2,%3}, [%4];"
                 : "=r"(r0), "=r"(r1), "=r"(r2), "=r"(r3) : "r"(addr));
}
__device__ __forceinline__ void mma_f16(float* c, const uint32_t* a, const uint32_t* b) {
    asm volatile(
        "mma.sync.aligned.m16n8k16.row.col.f32.f16.f16.f32 "
        "{%0,%1,%2,%3}, {%4,%5,%6,%7}, {%8,%9}, {%0,%1,%2,%3};"
        : "+f"(c[0]), "+f"(c[1]), "+f"(c[2]), "+f"(c[3])
        : "r"(a[0]), "r"(a[1]), "r"(a[2]), "r"(a[3]), "r"(b[0]), "r"(b[1]));
}
__device__ __forceinline__ float tanh_fast(float x) {
    float y;
    asm("tanh.approx.f32 %0, %1;" : "=f"(y) : "f"(x));
    return y;
}
__device__ __forceinline__ float gelu_fast(float v) {
    const float c0 = 0.7978845608028654f, c1 = 0.044715f;
    return 0.5f * v * (1.0f + tanh_fast(c0 * (v + c1 * v * v * v)));
}
__device__ __forceinline__ float ex2(float x) {   // 2^x, HW MUFU
    float y;
    asm("ex2.approx.f32 %0, %1;" : "=f"(y) : "f"(x));
    return y;
}

// ---------------------------------------------------------------------------
// weight prep: fp32 [K,N] -> half [N,K] (transpose + convert), per-layer via z
// ---------------------------------------------------------------------------
__global__ __launch_bounds__(256)
void prep_w_kernel(const float* __restrict__ src,
                   __half* __restrict__ dst, int K, int N) {
    __shared__ __half t[64][65];
    const size_t lo = (size_t)blockIdx.z * K * N;
    const int n0 = blockIdx.x * 64, k0 = blockIdx.y * 64;
    const int tx = threadIdx.x & 15, ty = threadIdx.x >> 4;   // 16x16

    #pragma unroll
    for (int ii = 0; ii < 4; ii++) {
        const int k = k0 + ty + ii * 16;
        const float4 v = *(const float4*)&src[lo + (size_t)k * N + n0 + tx * 4];
        t[tx * 4 + 0][ty + ii * 16] = __float2half(v.x);
        t[tx * 4 + 1][ty + ii * 16] = __float2half(v.y);
        t[tx * 4 + 2][ty + ii * 16] = __float2half(v.z);
        t[tx * 4 + 3][ty + ii * 16] = __float2half(v.w);
    }
    __syncthreads();

    const int w = threadIdx.x >> 5, l = threadIdx.x & 31;
    #pragma unroll
    for (int r = 0; r < 8; r++) {
        const int n = w * 8 + r;
        __half2 h = __halves2half2(t[n][2 * l], t[n][2 * l + 1]);
        *(uint32_t*)&dst[lo + (size_t)(n0 + n) * K + k0 + 2 * l] = *(uint32_t*)&h;
    }
}

// ---------------------------------------------------------------------------
// small per-layer checks: proj bias nonzero? ln1 params == ln2 params?
// ---------------------------------------------------------------------------
__global__ void smallprep_kernel(const float* __restrict__ proj_b,
                                 const float* __restrict__ l1g,
                                 const float* __restrict__ l1b,
                                 const float* __restrict__ l2g,
                                 const float* __restrict__ l2b,
                                 int* __restrict__ pbz,
                                 int* __restrict__ lneq) {
    const int l = blockIdx.x;
    const size_t o = (size_t)l * CDIM;
    int nz = 0, neq = 0;
    for (int i = threadIdx.x; i < CDIM; i += 256) {
        nz  |= (proj_b[o + i] != 0.0f);
        neq |= (l1g[o + i] != l2g[o + i]) | (l1b[o + i] != l2b[o + i]);
    }
    nz  = __syncthreads_or(nz);
    neq = __syncthreads_or(neq);
    if (threadIdx.x == 0) { pbz[l] = nz; lneq[l] = !neq; }
}

// ---------------------------------------------------------------------------
// LayerNorm (generic): ONE WARP per row. fp32 in -> fp16 out.
// If `pos` non-null (first layer): adds pos, writes fp32 x+pos to resout.
// If `flags` given (ln1), block 0 zeroes all flags (incl. anyWinner).
// If `anyw`/`lneq` given (ln2), early-exit when attention was identity and
// ln params match ln1 (xn already holds the correct values).
// ---------------------------------------------------------------------------
__global__ __launch_bounds__(256)
void ln_kernel(const float* __restrict__ in,
               const float* __restrict__ pos,
               float* __restrict__ resout,
               const float* __restrict__ g,
               const float* __restrict__ b,
               __half* __restrict__ out,
               int* __restrict__ flags,
               const int* __restrict__ anyw,
               const int* __restrict__ lneq) {
    if (anyw && lneq && lneq[0] != 0 && anyw[0] == 0) return;
    if (flags && blockIdx.x == 0 && threadIdx.x < NFLAGS) flags[threadIdx.x] = 0;

    const int row  = blockIdx.x * 8 + (threadIdx.x >> 5);
    const int lane = threadIdx.x & 31;
    const float4* rp = (const float4*)(in + (size_t)row * CDIM);
    const float4* pp = pos ? (const float4*)(pos + (size_t)(row & (NSEQ - 1)) * CDIM)
                           : nullptr;
    float4* ro = resout ? (float4*)(resout + (size_t)row * CDIM) : nullptr;

    float4 xv[8];
    float s = 0.f, sq = 0.f;
    #pragma unroll
    for (int i = 0; i < 8; i++) {
        xv[i] = rp[i * 32 + lane];
        if (pos) {
            const float4 p = pp[i * 32 + lane];
            xv[i].x += p.x; xv[i].y += p.y; xv[i].z += p.z; xv[i].w += p.w;
            ro[i * 32 + lane] = xv[i];
        }
        s  += xv[i].x + xv[i].y + xv[i].z + xv[i].w;
        sq += xv[i].x * xv[i].x + xv[i].y * xv[i].y
            + xv[i].z * xv[i].z + xv[i].w * xv[i].w;
    }
    #pragma unroll
    for (int o = 16; o > 0; o >>= 1) {
        s  += __shfl_xor_sync(0xffffffffu, s, o);
        sq += __shfl_xor_sync(0xffffffffu, sq, o);
    }
    const float mean = s * (1.0f / CDIM);
    const float var  = sq * (1.0f / CDIM) - mean * mean;
    const float rstd = rsqrtf(var + 1e-5f);

    const float4* gp = (const float4*)g;
    const float4* bp = (const float4*)b;
    uint2* op = (uint2*)(out + (size_t)row * CDIM);
    #pragma unroll
    for (int i = 0; i < 8; i++) {
        const float4 gg = gp[i * 32 + lane];
        const float4 bb = bp[i * 32 + lane];
        __half2 h0 = __floats2half2_rn((xv[i].x - mean) * rstd * gg.x + bb.x,
                                       (xv[i].y - mean) * rstd * gg.y + bb.y);
        __half2 h1 = __floats2half2_rn((xv[i].z - mean) * rstd * gg.z + bb.z,
                                       (xv[i].w - mean) * rstd * gg.w + bb.w);
        uint2 o;
        o.x = *(uint32_t*)&h0;
        o.y = *(uint32_t*)&h1;
        op[i * 32 + lane] = o;
    }
}

// ---------------------------------------------------------------------------
// FP16 tensor-core GEMM: C = A[M,K] @ Wt[N,K]^T + bias
// 128x128 CTA tile, BK=64, 256 threads, 3-stage cp.async pipeline with
// next-next tile's loads interleaved into the MMA ks-loop.
// ACT 1: gelu (half out), 2: +residual (fp32 out; tile-skip via flags and
//        full early-exit when bias is known-zero), 3: plain (half out),
// ACT 4: qk mode — half out; Q columns (bn < CDIM) scaled by score const.
// ---------------------------------------------------------------------------
template <int ACT, typename OUT_T>
__global__ __launch_bounds__(256, 2)
void hgemm_kernel(const __half* __restrict__ A,
                  const __half* __restrict__ Wt,
                  const float* __restrict__ bias,
                  const float* __restrict__ res,
                  OUT_T* __restrict__ C,
                  int M, int N, int K,
                  const int* __restrict__ flags,
                  const int* __restrict__ bias_nz) {
    extern __shared__ __half smh[];

    const int tid  = threadIdx.x;
    const int lane = tid & 31;
    const int warp = tid >> 5;
    const int wm = warp >> 2;
    const int wn = warp & 3;
    const int bm = blockIdx.y * 128;
    const int bn = blockIdx.x * 128;

    const bool skip = (ACT == 2) && flags && (flags[blockIdx.y] == 0);
    if (ACT == 2 && skip && bias_nz && bias_nz[0] == 0) return;  // out += 0

    float acc[4][4][4];
    #pragma unroll
    for (int i = 0; i < 4; i++)
        #pragma unroll
        for (int j = 0; j < 4; j++)
            #pragma unroll
            for (int t = 0; t < 4; t++) acc[i][j][t] = 0.f;

    if (!skip) {
        auto load_chunk = [&](int kt, int st, int part) {
            const __half* Ag = A  + (size_t)bm * K + kt * 64;
            const __half* Bg = Wt + (size_t)bn * K + kt * 64;
            __half* as = smh + st * STAGE_H;
            __half* bs = as + GEMM_TILE_H;
            int c = tid + part * 256;
            int r = c >> 3, seg = (c & 7) * 8;
            cp_async16((uint32_t)__cvta_generic_to_shared(as + r * LDH + seg),
                       Ag + (size_t)r * K + seg);
            cp_async16((uint32_t)__cvta_generic_to_shared(bs + r * LDH + seg),
                       Bg + (size_t)r * K + seg);
        };
        auto load_tile = [&](int kt, int st) {
            #pragma unroll
            for (int i = 0; i < 4; i++) load_chunk(kt, st, i);
        };

        const int KT = K / 64;
        load_tile(0, 0);
        cp_commit();
        load_tile(1, 1);
        cp_commit();

        const int a_row  = wm * 64 + (lane & 15);
        const int a_koff = (lane >> 4) * 8;
        const int b_g = lane >> 3;
        const int b_r = lane & 7;

        for (int kt = 0; kt < KT; kt++) {
            if (kt + 1 < KT) cp_wait1(); else cp_wait0();
            __syncthreads();
            const bool pf = (kt + 2 < KT);
            const int pfs = (kt + 2) % GEMM_STAGES;

            const __half* as = smh + (kt % GEMM_STAGES) * STAGE_H;
            const __half* bs = as + GEMM_TILE_H;
            #pragma unroll
            for (int ks = 0; ks < 4; ks++) {
                if (pf) load_chunk(kt + 2, pfs, ks);
                uint32_t a[4][4];
                #pragma unroll
                for (int mt = 0; mt < 4; mt++) {
                    uint32_t addr = (uint32_t)__cvta_generic_to_shared(
                        as + (a_row + mt * 16) * LDH + ks * 16 + a_koff);
                    ldsm_x4(a[mt][0], a[mt][1], a[mt][2], a[mt][3], addr);
                }
                uint32_t b[4][2];
                #pragma unroll
                for (int c = 0; c < 2; c++) {
                    int row = wn * 32 + (2 * c + (b_g >> 1)) * 8 + b_r;
                    int col = ks * 16 + (b_g & 1) * 8;
                    uint32_t addr = (uint32_t)__cvta_generic_to_shared(
                        bs + row * LDH + col);
                    ldsm_x4(b[2 * c][0], b[2 * c][1], b[2 * c + 1][0], b[2 * c + 1][1], addr);
                }
                #pragma unroll
                for (int mt = 0; mt < 4; mt++)
                    #pragma unroll
                    for (int nt = 0; nt < 4; nt++)
                        mma_f16(acc[mt][nt], a[mt], b[nt]);
            }
            if (pf) cp_commit();
        }
    }

    // fold score scale into Q' columns (qk mode); K tiles unscaled
    const float oscale = (ACT == 4 && bn < CDIM) ? ATT_SCALE_LOG2E : 1.0f;

    // Epilogue
    const int e_row = bm + wm * 64 + (lane >> 2);
    const int e_col = bn + wn * 32 + (lane & 3) * 2;
    #pragma unroll
    for (int mt = 0; mt < 4; mt++) {
        #pragma unroll
        for (int nt = 0; nt < 4; nt++) {
            const int col = e_col + nt * 8;
            const float bz0 = bias[col], bz1 = bias[col + 1];
            #pragma unroll
            for (int half_i = 0; half_i < 2; half_i++) {
                const int row = e_row + mt * 16 + half_i * 8;
                float v0 = acc[mt][nt][half_i * 2 + 0] + bz0;
                float v1 = acc[mt][nt][half_i * 2 + 1] + bz1;
                if (ACT == 1) {
                    v0 = gelu_fast(v0);
                    v1 = gelu_fast(v1);
                }
                if (ACT == 4) { v0 *= oscale; v1 *= oscale; }
                if (ACT == 2) {
                    const float2 r2 = *(const float2*)(res + (size_t)row * N + col);
                    v0 += r2.x; v1 += r2.y;
                    float2 o; o.x = v0; o.y = v1;
                    *(float2*)((float*)C + (size_t)row * N + col) = o;
                } else {
                    __half2 h = __floats2half2_rn(v0, v1);
                    *(uint32_t*)((__half*)C + (size_t)row * N + col) = *(uint32_t*)&h;
                }
            }
        }
    }
}

// ---------------------------------------------------------------------------
// FP16 tensor-core attention with hard threshold, base-2 un-normalized Z:
//   scores v are already in log2 domain (scale folded into Q').
//   Z_raw = sum 2^v   (half2 ex2, half2 accumulation — all terms positive)
//   winner prob = 2^m / Z_raw; out_row = prob > 0.5 ? prob*(xn[j*]@Wv+bv) : 0
// ---------------------------------------------------------------------------
__global__ __launch_bounds__(256, 3)
void attn_mma_kernel(const __half* __restrict__ qk,
                     const __half* __restrict__ xn,
                     const __half* __restrict__ wt,     // full qkv Wt[3C][C]
                     const float* __restrict__ qkv_b,
                     __half* __restrict__ out,
                     int* __restrict__ flags) {
    extern __shared__ __half smh[];
    __half* Qs = smh;                 // [64][LDH]
    __half* Ks = smh + ATTN_Q_H;      // [2 buf][128][LDH]

    __shared__ float part_m[64][4];
    __shared__ float part_z[64][4];
    __shared__ int   part_j[64][4];
    __shared__ float rscale[64];
    __shared__ int   rjmax[64];
    __shared__ int   s_any;

    const int bh = blockIdx.y;
    const int b  = bh >> 4;
    const int h  = bh & 15;
    const int r0 = blockIdx.x * 64;
    const int tid = threadIdx.x, lane = tid & 31, warp = tid >> 5;
    const int wm = warp >> 2, wn = warp & 3;

    if (tid == 0) s_any = 0;

    #pragma unroll
    for (int i = 0; i < 2; i++) {
        int c = tid + i * 256;
        int r = c >> 3, seg = (c & 7) * 8;
        const __half* src = qk + (size_t)(b * NSEQ + r0 + r) * 2 * CDIM
                            + h * HDIM + seg;
        cp_async16((uint32_t)__cvta_generic_to_shared(Qs + r * LDH + seg), src);
    }

    auto load_k = [&](int c0, int buf) {
        __half* base = Ks + buf * (128 * LDH);
        #pragma unroll
        for (int i = 0; i < 4; i++) {
            int c = tid + i * 256;
            int r = c >> 3, seg = (c & 7) * 8;
            const __half* src = qk + (size_t)(b * NSEQ + c0 + r) * 2 * CDIM
                                + CDIM + h * HDIM + seg;
            cp_async16((uint32_t)__cvta_generic_to_shared(base + r * LDH + seg), src);
        }
    };

    cp_commit();                 // Q group
    load_k(0, 0);
    cp_commit();

    float m_[4];
    __half2 Zh_[4];
    int j_[4];
    #pragma unroll
    for (int i = 0; i < 4; i++) {
        m_[i] = -1e30f;
        Zh_[i] = __float2half2_rn(0.f);
        j_[i] = 0;
    }

    const int b_g = lane >> 3;
    const int b_r = lane & 7;

    for (int kc = 0; kc < 8; kc++) {
        const int buf = kc & 1;
        cp_wait0();
        __syncthreads();
        if (kc < 7) { load_k((kc + 1) * 128, buf ^ 1); cp_commit(); }

        float acc[2][4][4];
        #pragma unroll
        for (int i = 0; i < 2; i++)
            #pragma unroll
            for (int j = 0; j < 4; j++)
                #pragma unroll
                for (int t = 0; t < 4; t++) acc[i][j][t] = 0.f;

        const __half* kb = Ks + buf * (128 * LDH);
        #pragma unroll
        for (int ks = 0; ks < 4; ks++) {
            uint32_t a[2][4];
            #pragma unroll
            for (int mt = 0; mt < 2; mt++) {
                uint32_t addr = (uint32_t)__cvta_generic_to_shared(
                    Qs + (wm * 32 + mt * 16 + (lane & 15)) * LDH
                       + ks * 16 + (lane >> 4) * 8);
                ldsm_x4(a[mt][0], a[mt][1], a[mt][2], a[mt][3], addr);
            }
            uint32_t bfr[4][2];
            #pragma unroll
            for (int c = 0; c < 2; c++) {
                int row = wn * 32 + (2 * c + (b_g >> 1)) * 8 + b_r;
                int col = ks * 16 + (b_g & 1) * 8;
                uint32_t addr = (uint32_t)__cvta_generic_to_shared(
                    kb + row * LDH + col);
                ldsm_x4(bfr[2 * c][0], bfr[2 * c][1], bfr[2 * c + 1][0], bfr[2 * c + 1][1], addr);
            }
            #pragma unroll
            for (int mt = 0; mt < 2; mt++)
                #pragma unroll
                for (int nt = 0; nt < 4; nt++)
                    mma_f16(acc[mt][nt], a[mt], bfr[nt]);
        }

        // online max/argmax + un-normalized Z (half2 ex2)
        #pragma unroll
        for (int mt = 0; mt < 2; mt++) {
            #pragma unroll
            for (int half_i = 0; half_i < 2; half_i++) {
                const int si = mt * 2 + half_i;
                const int bcol = kc * 128 + wn * 32 + (lane & 3) * 2;
                float v[8];
                #pragma unroll
                for (int nt = 0; nt < 4; nt++) {
                    v[nt * 2 + 0] = acc[mt][nt][half_i * 2 + 0];
                    v[nt * 2 + 1] = acc[mt][nt][half_i * 2 + 1];
                }
                float m01 = fmaxf(v[0], v[1]), m23 = fmaxf(v[2], v[3]);
                float m45 = fmaxf(v[4], v[5]), m67 = fmaxf(v[6], v[7]);
                float cmax = fmaxf(fmaxf(m01, m23), fmaxf(m45, m67));
                if (cmax > m_[si]) {
                    int cj = bcol;
                    #pragma unroll
                    for (int q = 1; q < 8; q++)
                        if (v[q] == cmax) cj = bcol + (q >> 1) * 8 + (q & 1);
                    m_[si] = cmax;
                    j_[si] = cj;
                }
                #pragma unroll
                for (int p = 0; p < 4; p++) {
                    __half2 hv = __floats2half2_rn(v[2 * p], v[2 * p + 1]);
                    Zh_[si] = __hadd2(Zh_[si], h2exp2(hv));
                }
            }
        }
    }

    // quad (lane&3) reduce (plain sum + max/argmax), then cross-warp reduce
    #pragma unroll
    for (int si = 0; si < 4; si++) {
        const float2 zf = __half22float2(Zh_[si]);
        float mm = m_[si], zz = zf.x + zf.y;
        int jj = j_[si];
        #pragma unroll
        for (int o = 1; o <= 2; o <<= 1) {
            float om = __shfl_xor_sync(0xffffffffu, mm, o);
            float oz = __shfl_xor_sync(0xffffffffu, zz, o);
            int   oj = __shfl_xor_sync(0xffffffffu, jj, o);
            zz += oz;
            if (om > mm) { mm = om; jj = oj; }
        }
        if ((lane & 3) == 0) {
            int row = wm * 32 + (si >> 1) * 16 + (si & 1) * 8 + (lane >> 2);
            part_m[row][wn] = mm;
            part_z[row][wn] = zz;
            part_j[row][wn] = jj;
        }
    }
    __syncthreads();

    if (tid < 64) {
        float mm = part_m[tid][0], zz = part_z[tid][0];
        int jj = part_j[tid][0];
        #pragma unroll
        for (int t = 1; t < 4; t++) {
            const float om = part_m[tid][t];
            zz += part_z[tid][t];
            if (om > mm) { mm = om; jj = part_j[tid][t]; }
        }
        const float amax = ex2(mm) / zz;       // winner probability
        const float sc = (amax > 0.5f) ? amax : 0.0f;
        rscale[tid] = sc;
        rjmax[tid]  = jj;
        if (sc != 0.0f) s_any = 1;
    }
    __syncthreads();

    if (tid == 0 && s_any) {
        atomicOr(&flags[(b * NSEQ + r0) >> 7], 1);
        atomicOr(&flags[NFLAGS - 1], 1);          // per-layer anyWinner
    }

    const int r  = tid >> 2;
    const int d0 = (tid & 3) * 16;
    const float sc = rscale[r];
    const int jj = rjmax[r];
    __half* orow = out + (size_t)(b * NSEQ + r0 + r) * CDIM + h * HDIM;
    if (sc != 0.0f) {
        const __half* xrow = xn + (size_t)(b * NSEQ + jj) * CDIM;
        #pragma unroll 1
        for (int d = d0; d < d0 + 16; d++) {
            const __half* wrow = wt + (size_t)(2 * CDIM + h * HDIM + d) * CDIM;
            float accv = 0.f;
            const __half2* xp = (const __half2*)xrow;
            const __half2* wp = (const __half2*)wrow;
            #pragma unroll 8
            for (int k2 = 0; k2 < CDIM / 2; k2++) {
                float2 xf = __half22float2(xp[k2]);
                float2 wf = __half22float2(wp[k2]);
                accv += xf.x * wf.x + xf.y * wf.y;
            }
            accv += qkv_b[2 * CDIM + h * HDIM + d];
            orow[d] = __float2half(accv * sc);
        }
    } else {
        uint4 z; z.x = 0u; z.y = 0u; z.z = 0u; z.w = 0u;
        *(uint4*)(orow + d0) = z;
        *(uint4*)(orow + d0 + 8) = z;
    }
}

// ---------------------------------------------------------------------------
extern "C" void kernel_launch(void* const* d_in, const int* in_sizes, int n_in,
                              void* d_out, int out_size) {
    (void)in_sizes; (void)n_in; (void)out_size;
    const float* x      = (const float*)d_in[0];
    const float* pos    = (const float*)d_in[1];
    const float* qkv_w  = (const float*)d_in[2];
    const float* qkv_b  = (const float*)d_in[3];
    const float* proj_w = (const float*)d_in[4];
    const float* proj_b = (const float*)d_in[5];
    const float* ln1_g  = (const float*)d_in[6];
    const float* ln1_b  = (const float*)d_in[7];
    const float* ln2_g  = (const float*)d_in[8];
    const float* ln2_b  = (const float*)d_in[9];
    const float* fc1_w  = (const float*)d_in[10];
    const float* fc1_b  = (const float*)d_in[11];
    const float* fc2_w  = (const float*)d_in[12];
    const float* fc2_b  = (const float*)d_in[13];
    float* out = (float*)d_out;

    __half *xn, *qk, *attn, *ff, *wq, *wp, *w1, *w2;
    int *flags, *pbz, *lneq;
    cudaGetSymbolAddress((void**)&xn,   g_xn);
    cudaGetSymbolAddress((void**)&qk,   g_qk);
    cudaGetSymbolAddress((void**)&attn, g_attn);
    cudaGetSymbolAddress((void**)&ff,   g_ff);
    cudaGetSymbolAddress((void**)&wq,   g_wq);
    cudaGetSymbolAddress((void**)&wp,   g_wp);
    cudaGetSymbolAddress((void**)&w1,   g_w1);
    cudaGetSymbolAddress((void**)&w2,   g_w2);
    cudaGetSymbolAddress((void**)&flags, g_flags);
    cudaGetSymbolAddress((void**)&pbz,  g_pbz);
    cudaGetSymbolAddress((void**)&lneq, g_lneq);

    cudaFuncSetAttribute(hgemm_kernel<1, __half>,
                         cudaFuncAttributeMaxDynamicSharedMemorySize, GEMM_SMEM_BYTES);
    cudaFuncSetAttribute(hgemm_kernel<2, float>,
                         cudaFuncAttributeMaxDynamicSharedMemorySize, GEMM_SMEM_BYTES);
    cudaFuncSetAttribute(hgemm_kernel<4, __half>,
                         cudaFuncAttributeMaxDynamicSharedMemorySize, GEMM_SMEM_BYTES);
    cudaFuncSetAttribute(attn_mma_kernel,
                         cudaFuncAttributeMaxDynamicSharedMemorySize, ATTN_SMEM_BYTES);

    // weight prep: fp16 convert + transpose [K,N] -> [N,K] (once per launch)
    prep_w_kernel<<<dim3(3 * CDIM / 64, CDIM / 64, LAYERS), 256>>>(qkv_w,  wq, CDIM, 3 * CDIM);
    prep_w_kernel<<<dim3(CDIM / 64,     CDIM / 64, LAYERS), 256>>>(proj_w, wp, CDIM, CDIM);
    prep_w_kernel<<<dim3(FFD / 64,      CDIM / 64, LAYERS), 256>>>(fc1_w,  w1, CDIM, FFD);
    prep_w_kernel<<<dim3(CDIM / 64,     FFD / 64,  LAYERS), 256>>>(fc2_w,  w2, FFD, CDIM);
    smallprep_kernel<<<LAYERS, 256>>>(proj_b, ln1_g, ln1_b, ln2_g, ln2_b, pbz, lneq);

    for (int l = 0; l < LAYERS; l++) {
        const __half* wql = wq + (size_t)l * CDIM * 3 * CDIM;
        // --- attention block ---
        if (l == 0) {
            // fused: out = x + pos;  xn = LN(out)
            ln_kernel<<<TOK / 8, 256>>>(x, pos, out,
                                        ln1_g, ln1_b, xn, flags, nullptr, nullptr);
        } else {
            ln_kernel<<<TOK / 8, 256>>>(out, nullptr, nullptr,
                                        ln1_g + (size_t)l * CDIM,
                                        ln1_b + (size_t)l * CDIM, xn, flags,
                                        nullptr, nullptr);
        }
        // Q,K only (Wt rows 0..2C): N = 2048; Q columns pre-scaled (ACT=4)
        hgemm_kernel<4, __half><<<dim3(2 * CDIM / 128, TOK / 128), 256, GEMM_SMEM_BYTES>>>(
            xn, wql, qkv_b + (size_t)l * 3 * CDIM,
            nullptr, qk, TOK, 2 * CDIM, CDIM, nullptr, nullptr);
        attn_mma_kernel<<<dim3(NSEQ / 64, BSZ * HEADS), 256, ATTN_SMEM_BYTES>>>(
            qk, xn, wql, qkv_b + (size_t)l * 3 * CDIM, attn, flags);
        hgemm_kernel<2, float><<<dim3(CDIM / 128, TOK / 128), 256, GEMM_SMEM_BYTES>>>(
            attn, wp + (size_t)l * CDIM * CDIM, proj_b + (size_t)l * CDIM,
            out, out, TOK, CDIM, CDIM, flags, pbz + l);
        // --- MLP block ---
        ln_kernel<<<TOK / 8, 256>>>(out, nullptr, nullptr,
                                    ln2_g + (size_t)l * CDIM,
                                    ln2_b + (size_t)l * CDIM, xn, nullptr,
                                    flags + NFLAGS - 1, lneq + l);
        hgemm_kernel<1, __half><<<dim3(FFD / 128, TOK / 128), 256, GEMM_SMEM_BYTES>>>(
            xn, w1 + (size_t)l * CDIM * FFD, fc1_b + (size_t)l * FFD,
            nullptr, ff, TOK, FFD, CDIM, nullptr, nullptr);
        hgemm_kernel<2, float><<<dim3(CDIM / 128, TOK / 128), 256, GEMM_SMEM_BYTES>>>(
            ff, w2 + (size_t)l * FFD * CDIM, fc2_b + (size_t)l * CDIM,
            out, out, TOK, CDIM, FFD, nullptr, nullptr);
    }
}